// round 11
// baseline (speedup 1.0000x reference)
#include <cuda_runtime.h>
#include <cuda_bf16.h>

#define N_NODES 50000
#define N_EDGES 1200000
#define DIM 64
#define SCAN_B 49   // ceil(50000/1024)

// Scratch (allocation-free __device__ globals)
__device__ __align__(16) float g_Henc[N_NODES * DIM];        // layer output H_l (fp32)
__device__ __align__(16) unsigned int g_Hb[N_NODES * DIM/2]; // bf16x2 of dis[u]*H_l[u]
__device__ __align__(16) float g_agg [N_NODES * DIM];        // P = (S+I)H
__device__ __align__(16) int   g_deg [N_NODES];              // out-degree over u
__device__ __align__(16) int   g_cnt [N_NODES];              // in-degree over v
__device__ __align__(16) int   g_fill[N_NODES];              // fill cursor per v
__device__ __align__(16) int   g_rowstart[N_NODES + 1];      // CSR row offsets (by v)
__device__ __align__(16) int2  g_uv  [N_EDGES];              // decoded (u,v)
__device__ __align__(16) int   g_csr [N_EDGES];              // u sorted by v
__device__ __align__(16) float g_svp [N_NODES];              // 1 + dis_v * sum dis_u
__device__ __align__(16) float g_Wc  [3 * DIM * DIM];        // composite We@Wu per layer
__device__ __align__(16) float g_c2  [3 * DIM];              // be@Wu per layer
__device__ __align__(16) float g_sum64[DIM];
__device__ __align__(16) int   g_bsum[SCAN_B];               // per-block cnt sums
__device__ int g_done;   // last-block ticket for fused readout

// ---------------------------------------------------------------------------
// Init: zero counters/sums.
__global__ void __launch_bounds__(256) k_init() {
    int i = blockIdx.x * 256 + threadIdx.x;
    if (i < N_NODES) { g_deg[i] = 0; g_cnt[i] = 0; g_fill[i] = 0; }
    if (i < DIM)     g_sum64[i] = 0.f;
    if (i == 0)      g_done = 0;
}

// Decode edge index -> int2 uv, histogram deg(u) / cnt(v). 2 edges per thread.
// Per-block dtype vote: block reads its own span's high words; if edge_index
// is int64 all high words are < 50000's zero-extension (0); if int32 the
// "high words" are random node indices (P(all 512 zero) ~ 0).
__global__ void __launch_bounds__(256) k_prep(const void* __restrict__ eiv) {
    int p = blockIdx.x * 256 + threadIdx.x;       // pair index
    int i = p * 2;

    __shared__ unsigned int vote;
    if (threadIdx.x == 0) vote = 0u;
    __syncthreads();
    unsigned int hi = 0;
    if (i < N_EDGES) {
        const unsigned long long* e64 = (const unsigned long long*)eiv;
        hi = (unsigned int)(e64[p] >> 32) | (unsigned int)(e64[p + 1 < N_EDGES ? p + 1 : p] >> 32);
    }
    atomicOr(&vote, hi);
    __syncthreads();
    int is32 = (vote != 0u);

    if (i >= N_EDGES) return;
    int u0, u1, v0, v1;
    if (is32) {
        const int2* e = (const int2*)eiv;
        int2 up = e[p];
        int2 vp = ((const int2*)((const int*)eiv + N_EDGES))[p];
        u0 = up.x; u1 = up.y; v0 = vp.x; v1 = vp.y;
    } else {
        const longlong2* e = (const longlong2*)eiv;
        longlong2 up = e[p];
        longlong2 vp = ((const longlong2*)((const long long*)eiv + N_EDGES))[p];
        u0 = (int)up.x; u1 = (int)up.y; v0 = (int)vp.x; v1 = (int)vp.y;
    }
    u0 = min(max(u0, 0), N_NODES - 1); u1 = min(max(u1, 0), N_NODES - 1);
    v0 = min(max(v0, 0), N_NODES - 1); v1 = min(max(v1, 0), N_NODES - 1);
    ((int4*)g_uv)[p] = make_int4(u0, v0, u1, v1);
    atomicAdd(&g_deg[u0], 1);
    atomicAdd(&g_deg[u1], 1);
    atomicAdd(&g_cnt[v0], 1);
    atomicAdd(&g_cnt[v1], 1);
}

// Per-block sums of g_cnt (49 blocks x 1024)
__global__ void __launch_bounds__(1024) k_bsum() {
    int t = threadIdx.x;
    int i = blockIdx.x * 1024 + t;
    int val = (i < N_NODES) ? g_cnt[i] : 0;
#pragma unroll
    for (int o = 16; o; o >>= 1) val += __shfl_xor_sync(0xffffffffu, val, o);
    __shared__ int ws[32];
    if ((t & 31) == 0) ws[t >> 5] = val;
    __syncthreads();
    if (t < 32) {
        int v = ws[t];
#pragma unroll
        for (int o = 16; o; o >>= 1) v += __shfl_xor_sync(0xffffffffu, v, o);
        if (t == 0) g_bsum[blockIdx.x] = v;
    }
}

// Block-local exclusive scan + global base -> g_rowstart
__global__ void __launch_bounds__(1024) k_scan2() {
    int t = threadIdx.x;
    int b = blockIdx.x;
    int i = b * 1024 + t;
    __shared__ int sbase;
    __shared__ int ws[32];
    if (t == 0) {
        int acc = 0;
        for (int j = 0; j < b; j++) acc += g_bsum[j];
        sbase = acc;
    }
    int orig = (i < N_NODES) ? g_cnt[i] : 0;
    int val = orig;
    int lane = t & 31;
#pragma unroll
    for (int o = 1; o < 32; o <<= 1) {
        int n = __shfl_up_sync(0xffffffffu, val, o);
        if (lane >= o) val += n;
    }
    if (lane == 31) ws[t >> 5] = val;
    __syncthreads();
    if (t < 32) {
        int v = ws[t];
#pragma unroll
        for (int o = 1; o < 32; o <<= 1) {
            int n = __shfl_up_sync(0xffffffffu, v, o);
            if (t >= o) v += n;
        }
        ws[t] = v;   // inclusive warp-sums
    }
    __syncthreads();
    int woff = (t >= 32) ? ws[(t >> 5) - 1] : 0;
    int excl = sbase + woff + (val - orig);
    if (i < N_NODES) {
        g_rowstart[i] = excl;
        if (i == N_NODES - 1) g_rowstart[N_NODES] = excl + orig;
    }
}

// Scatter edges into CSR slots (sorted by v); payload = u only
__global__ void __launch_bounds__(256) k_fill() {
    int i = blockIdx.x * 256 + threadIdx.x;
    if (i >= N_EDGES) return;
    int2 uv = g_uv[i];
    int pos = g_rowstart[uv.y] + atomicAdd(&g_fill[uv.y], 1);
    g_csr[pos] = uv.x;
}

// Per-node s factor: svp_v = 1 + dis_v * sum_{u in N(v)} dis_u
__global__ void __launch_bounds__(256) k_svec() {
    int v = blockIdx.x * 256 + threadIdx.x;
    if (v >= N_NODES) return;
    int s = g_rowstart[v], e = g_rowstart[v + 1];
    float s0 = 0.f, s1 = 0.f, s2 = 0.f, s3 = 0.f;
    int i = s;
    for (; i + 4 <= e; i += 4) {
        int u0 = g_csr[i], u1 = g_csr[i+1], u2 = g_csr[i+2], u3 = g_csr[i+3];
        s0 += rsqrtf((float)g_deg[u0] + 1.f);
        s1 += rsqrtf((float)g_deg[u1] + 1.f);
        s2 += rsqrtf((float)g_deg[u2] + 1.f);
        s3 += rsqrtf((float)g_deg[u3] + 1.f);
    }
    for (; i < e; i++) s0 += rsqrtf((float)g_deg[g_csr[i]] + 1.f);
    float sum = (s0 + s1) + (s2 + s3);
    g_svp[v] = 1.f + rsqrtf((float)g_deg[v] + 1.f) * sum;
}

// Composite weights: Wc_l = We_l @ Wu_l, c2_l = be_l @ Wu_l. One block per layer.
__global__ void __launch_bounds__(256) k_wprep(
    const float* __restrict__ We0, const float* __restrict__ Be0, const float* __restrict__ Wu0,
    const float* __restrict__ We1, const float* __restrict__ Be1, const float* __restrict__ Wu1,
    const float* __restrict__ We2, const float* __restrict__ Be2, const float* __restrict__ Wu2)
{
    int l = blockIdx.x;
    const float* We = (l == 0) ? We0 : (l == 1) ? We1 : We2;
    const float* Be = (l == 0) ? Be0 : (l == 1) ? Be1 : Be2;
    const float* Wu = (l == 0) ? Wu0 : (l == 1) ? Wu1 : Wu2;
    __shared__ float sWe[DIM * DIM], sWu[DIM * DIM];
    int t = threadIdx.x;
    for (int i = t; i < DIM * DIM; i += 256) { sWe[i] = We[i]; sWu[i] = Wu[i]; }
    __syncthreads();
    for (int o = t; o < DIM * DIM; o += 256) {
        int i = o >> 6, j = o & 63;
        float acc = 0.f;
#pragma unroll 8
        for (int k = 0; k < DIM; k++)
            acc = fmaf(sWe[i * DIM + k], sWu[k * DIM + j], acc);
        g_Wc[l * DIM * DIM + o] = acc;
    }
    if (t < DIM) {
        float acc = 0.f;
#pragma unroll 8
        for (int k = 0; k < DIM; k++)
            acc = fmaf(Be[k], sWu[k * DIM + t], acc);
        g_c2[l * DIM + t] = acc;
    }
}

// Build layer-0 gather table: g_Hb = bf16(dis[node] * X[node])
__global__ void __launch_bounds__(256) k_hb0(const float* __restrict__ X) {
    int idx = blockIdx.x * 256 + threadIdx.x;   // node*16 + c
    if (idx >= N_NODES * 16) return;
    int node = idx >> 4;
    float dis = rsqrtf((float)g_deg[node] + 1.f);
    float4 v = ((const float4*)X)[idx];
    __nv_bfloat162 b0 = __floats2bfloat162_rn(v.x * dis, v.y * dis);
    __nv_bfloat162 b1 = __floats2bfloat162_rn(v.z * dis, v.w * dis);
    ((uint2*)g_Hb)[idx] = make_uint2(*(unsigned int*)&b0, *(unsigned int*)&b1);
}

// ---------------------------------------------------------------------------
// bf16x2-pair add helper (dis_u pre-folded into Hb)
__device__ __forceinline__ void bf16add(float4& a, uint2 p) {
    float2 lo = __bfloat1622float2(*(__nv_bfloat162*)&p.x);
    float2 hi = __bfloat1622float2(*(__nv_bfloat162*)&p.y);
    a.x += lo.x; a.y += lo.y; a.z += hi.x; a.w += hi.y;
}

// Pull aggregation incl self: P[v] = dis_v * sum_e Hb[u_e] + self[v]
__global__ void __launch_bounds__(256) k_agg(const float* __restrict__ X, int use_gH) {
    int idx = blockIdx.x * 256 + threadIdx.x;
    int node = idx >> 4;
    if (node >= N_NODES) return;
    int c = idx & 15;
    int s = g_rowstart[node];
    int e = g_rowstart[node + 1];
    const uint2* __restrict__ Hb = (const uint2*)g_Hb;
    const float* self = use_gH ? g_Henc : X;

    float4 a0 = make_float4(0.f, 0.f, 0.f, 0.f);
    float4 a1 = make_float4(0.f, 0.f, 0.f, 0.f);
    float4 a2 = make_float4(0.f, 0.f, 0.f, 0.f);
    float4 a3 = make_float4(0.f, 0.f, 0.f, 0.f);

    int i = s;
    for (; i + 4 <= e; i += 4) {
        int u0 = g_csr[i];
        int u1 = g_csr[i + 1];
        int u2 = g_csr[i + 2];
        int u3 = g_csr[i + 3];
        uint2 p0 = Hb[u0 * 16 + c];
        uint2 p1 = Hb[u1 * 16 + c];
        uint2 p2 = Hb[u2 * 16 + c];
        uint2 p3 = Hb[u3 * 16 + c];
        bf16add(a0, p0);
        bf16add(a1, p1);
        bf16add(a2, p2);
        bf16add(a3, p3);
    }
    for (; i < e; i++) {
        uint2 p0 = Hb[g_csr[i] * 16 + c];
        bf16add(a0, p0);
    }

    float dv = rsqrtf((float)g_deg[node] + 1.0f);
    float4 sf = ((const float4*)self)[node * 16 + c];
    float4 acc;
    acc.x = fmaf(dv, (a0.x + a1.x) + (a2.x + a3.x), sf.x);
    acc.y = fmaf(dv, (a0.y + a1.y) + (a2.y + a3.y), sf.y);
    acc.z = fmaf(dv, (a0.z + a1.z) + (a2.z + a3.z), sf.z);
    acc.w = fmaf(dv, (a0.w + a1.w) + (a2.w + a3.w), sf.w);
    ((float4*)g_agg)[node * 16 + c] = acc;
}

// ---------------------------------------------------------------------------
// GEMM inner: x preloaded in registers (MLP=16 on input loads), W from shared.
__device__ __forceinline__ void gemm_regs(
    const float4* __restrict__ x,   // 16 float4 in registers
    const float4* __restrict__ Ws,
    float4* __restrict__ acc)
{
#pragma unroll 4
    for (int kk = 0; kk < 16; kk++) {
        float4 hv = x[kk];
#pragma unroll
        for (int kc = 0; kc < 4; kc++) {
            float hk = (kc == 0) ? hv.x : (kc == 1) ? hv.y : (kc == 2) ? hv.z : hv.w;
            const float4* wrow = Ws + (kk * 4 + kc) * 16;
#pragma unroll
            for (int j = 0; j < 16; j++) {
                float4 w = wrow[j];
                acc[j].x = fmaf(hk, w.x, acc[j].x);
                acc[j].y = fmaf(hk, w.y, acc[j].y);
                acc[j].z = fmaf(hk, w.z, acc[j].z);
                acc[j].w = fmaf(hk, w.w, acc[j].w);
            }
        }
    }
}

// Layer GEMM (one per layer): H' = relu(P @ Wc + bu + svp*c2).
// One row per thread, full-row register preload.
__global__ void __launch_bounds__(128) k_layer(
    int l, const float* __restrict__ Bu)
{
    __shared__ float4 Ws[1024];
    __shared__ float  B1[64], B2[64];
    int tid = threadIdx.x;
    const float4* W4 = (const float4*)(g_Wc + l * DIM * DIM);
#pragma unroll
    for (int i = 0; i < 8; i++) Ws[tid + 128 * i] = W4[tid + 128 * i];
    if (tid < 64) { B1[tid] = Bu[tid]; B2[tid] = g_c2[l * DIM + tid]; }
    __syncthreads();

    int row = blockIdx.x * 128 + tid;
    if (row >= N_NODES) return;
    float svp = g_svp[row];

    // Preload input row (16 independent LDG.128)
    float4 x[16];
    const float4* xr = (const float4*)(g_agg + row * DIM);
#pragma unroll
    for (int j = 0; j < 16; j++) x[j] = xr[j];

    float4 acc[16];
#pragma unroll
    for (int j = 0; j < 16; j++)
        acc[j] = make_float4(fmaf(svp, B2[4*j],   B1[4*j]),
                             fmaf(svp, B2[4*j+1], B1[4*j+1]),
                             fmaf(svp, B2[4*j+2], B1[4*j+2]),
                             fmaf(svp, B2[4*j+3], B1[4*j+3]));
    gemm_regs(x, Ws, acc);

    float dis = rsqrtf((float)g_deg[row] + 1.0f);
    float4* o32 = (float4*)(g_Henc + row * DIM);
    uint2*  ob  = (uint2*)(g_Hb + row * (DIM/2));
#pragma unroll
    for (int j = 0; j < 16; j++) {
        float4 v = acc[j];
        v.x = fmaxf(v.x, 0.f); v.y = fmaxf(v.y, 0.f);
        v.z = fmaxf(v.z, 0.f); v.w = fmaxf(v.w, 0.f);
        o32[j] = v;
        __nv_bfloat162 b0 = __floats2bfloat162_rn(v.x * dis, v.y * dis);
        __nv_bfloat162 b1 = __floats2bfloat162_rn(v.z * dis, v.w * dis);
        ob[j] = make_uint2(*(unsigned int*)&b0, *(unsigned int*)&b1);
    }
}

// Final layer GEMM + mean-readout + last-block finalize.
__global__ void __launch_bounds__(128) k_layer_sum(
    int l, const float* __restrict__ Bu,
    const float* __restrict__ out_w, const float* __restrict__ out_b,
    float* __restrict__ out)
{
    __shared__ float4 Ws[1024];
    __shared__ float  B1[64], B2[64];
    __shared__ float  ssum[64];
    int tid = threadIdx.x;
    const float4* W4 = (const float4*)(g_Wc + l * DIM * DIM);
#pragma unroll
    for (int i = 0; i < 8; i++) Ws[tid + 128 * i] = W4[tid + 128 * i];
    if (tid < 64) { B1[tid] = Bu[tid]; B2[tid] = g_c2[l * DIM + tid]; ssum[tid] = 0.f; }
    __syncthreads();

    int row = blockIdx.x * 128 + tid;
    bool valid = (row < N_NODES);

    float4 acc[16];
    if (valid) {
        float svp = g_svp[row];
        float4 x[16];
        const float4* xr = (const float4*)(g_agg + row * DIM);
#pragma unroll
        for (int j = 0; j < 16; j++) x[j] = xr[j];
#pragma unroll
        for (int j = 0; j < 16; j++)
            acc[j] = make_float4(fmaf(svp, B2[4*j],   B1[4*j]),
                                 fmaf(svp, B2[4*j+1], B1[4*j+1]),
                                 fmaf(svp, B2[4*j+2], B1[4*j+2]),
                                 fmaf(svp, B2[4*j+3], B1[4*j+3]));
        gemm_regs(x, Ws, acc);
#pragma unroll
        for (int j = 0; j < 16; j++) {
            acc[j].x = fmaxf(acc[j].x, 0.f); acc[j].y = fmaxf(acc[j].y, 0.f);
            acc[j].z = fmaxf(acc[j].z, 0.f); acc[j].w = fmaxf(acc[j].w, 0.f);
        }
    } else {
#pragma unroll
        for (int j = 0; j < 16; j++) acc[j] = make_float4(0.f, 0.f, 0.f, 0.f);
    }

    int lane = tid & 31;
#pragma unroll
    for (int j = 0; j < 16; j++) {
#pragma unroll
        for (int kc = 0; kc < 4; kc++) {
            float v = (kc == 0) ? acc[j].x : (kc == 1) ? acc[j].y : (kc == 2) ? acc[j].z : acc[j].w;
#pragma unroll
            for (int o = 16; o; o >>= 1) v += __shfl_xor_sync(0xffffffffu, v, o);
            if (lane == 0) atomicAdd(&ssum[4 * j + kc], v);
        }
    }
    __syncthreads();
    if (tid < 64) atomicAdd(&g_sum64[tid], ssum[tid]);

    __threadfence();
    __shared__ int isLast;
    if (tid == 0) {
        int p = atomicAdd(&g_done, 1);
        isLast = (p == (int)gridDim.x - 1) ? 1 : 0;
    }
    __syncthreads();
    if (isLast && tid < 32) {
        float p = g_sum64[tid] * out_w[tid] + g_sum64[tid + 32] * out_w[tid + 32];
#pragma unroll
        for (int o = 16; o; o >>= 1) p += __shfl_down_sync(0xffffffffu, p, o);
        if (tid == 0) out[0] = p / (float)N_NODES + out_b[0];
    }
}

// ---------------------------------------------------------------------------
extern "C" void kernel_launch(void* const* d_in, const int* in_sizes, int n_in,
                              void* d_out, int out_size)
{
    const float* H  = (const float*)d_in[0];
    const void*  ei = d_in[1];
    // d_in[2] = E (unused by reference GCN path)
    const float* enc_w[3] = {(const float*)d_in[3],  (const float*)d_in[7],  (const float*)d_in[11]};
    const float* enc_b[3] = {(const float*)d_in[4],  (const float*)d_in[8],  (const float*)d_in[12]};
    const float* upd_w[3] = {(const float*)d_in[5],  (const float*)d_in[9],  (const float*)d_in[13]};
    const float* upd_b[3] = {(const float*)d_in[6],  (const float*)d_in[10], (const float*)d_in[14]};
    const float* out_w = (const float*)d_in[15];
    const float* out_b = (const float*)d_in[16];
    float* out = (float*)d_out;

    const int EB  = (N_EDGES + 255) / 256;            // 4688
    const int PB  = (N_EDGES / 2 + 255) / 256;        // 2344
    const int NB  = (N_NODES + 255) / 256;            // 196
    const int GB  = (N_NODES + 127) / 128;            // 391
    const int AB  = (N_NODES * 16 + 255) / 256;       // 3125

    k_init <<<NB, 256>>>();
    k_prep <<<PB, 256>>>(ei);
    k_bsum <<<SCAN_B, 1024>>>();
    k_scan2<<<SCAN_B, 1024>>>();
    k_fill <<<EB, 256>>>();
    k_svec <<<NB, 256>>>();
    k_wprep<<<3, 256>>>(enc_w[0], enc_b[0], upd_w[0],
                        enc_w[1], enc_b[1], upd_w[1],
                        enc_w[2], enc_b[2], upd_w[2]);
    k_hb0  <<<AB, 256>>>(H);

    k_agg  <<<AB, 256>>>(H, 0);              // P0 = (S+I)X
    k_layer<<<GB, 128>>>(0, upd_b[0]);       // H1
    k_agg  <<<AB, 256>>>(H, 1);              // P1 = (S+I)H1
    k_layer<<<GB, 128>>>(1, upd_b[1]);       // H2
    k_agg  <<<AB, 256>>>(H, 1);              // P2 = (S+I)H2
    k_layer_sum<<<GB, 128>>>(2, upd_b[2], out_w, out_b, out);
}

// round 12
// speedup vs baseline: 1.0016x; 1.0016x over previous
#include <cuda_runtime.h>
#include <cuda_bf16.h>

#define N_NODES 50000
#define N_EDGES 1200000
#define DIM 64
#define SCAN_B 49   // ceil(50000/1024)

// Scratch (allocation-free __device__ globals)
__device__ __align__(16) float g_Henc[N_NODES * DIM];        // layer output H_l (fp32)
__device__ __align__(16) unsigned int g_Hb[N_NODES * DIM/2]; // bf16x2 of dis[u]*H_l[u]
__device__ __align__(16) float g_agg [N_NODES * DIM];        // P = (S+I)H
__device__ __align__(16) int   g_deg [N_NODES];              // out-degree over u
__device__ __align__(16) int   g_cnt [N_NODES];              // in-degree over v
__device__ __align__(16) int   g_fill[N_NODES];              // fill cursor per v
__device__ __align__(16) int   g_rowstart[N_NODES + 1];      // CSR row offsets (by v)
__device__ __align__(16) int2  g_uv  [N_EDGES];              // decoded (u,v)
__device__ __align__(16) int   g_csr [N_EDGES];              // u sorted by v
__device__ __align__(16) float g_svp [N_NODES];              // 1 + dis_v * sum dis_u
__device__ __align__(16) float g_Wc  [3 * DIM * DIM];        // composite We@Wu per layer
__device__ __align__(16) float g_c2  [3 * DIM];              // be@Wu per layer
__device__ __align__(16) float g_sum64[DIM];
__device__ __align__(16) int   g_bsum[SCAN_B];               // per-block cnt sums
__device__ int g_is32;   // 1 if edge_index is int32 on device
__device__ int g_done;   // last-block ticket for fused readout

// ---------------------------------------------------------------------------
// Init: block 0 probes edge_index dtype; all blocks zero counters/sums.
__global__ void __launch_bounds__(256) k_init(const unsigned long long* __restrict__ ei) {
    int i = blockIdx.x * 256 + threadIdx.x;
    if (i < N_NODES) { g_deg[i] = 0; g_cnt[i] = 0; g_fill[i] = 0; }
    if (i < DIM)     g_sum64[i] = 0.f;
    if (i == 0)      g_done = 0;
    if (blockIdx.x == 0) {
        int t = threadIdx.x;
        unsigned int any = 0;
        for (int j = t; j < 2048; j += 256)
            any |= (unsigned int)(ei[j] >> 32);
        __shared__ unsigned int s;
        if (t == 0) s = 0u;
        __syncthreads();
        atomicOr(&s, any);
        __syncthreads();
        if (t == 0) g_is32 = (s != 0u) ? 1 : 0;
    }
}

// Decode edge index -> int2 uv, histogram deg(u) / cnt(v). 2 edges per thread.
__global__ void __launch_bounds__(256) k_prep(const void* __restrict__ eiv) {
    int p = blockIdx.x * 256 + threadIdx.x;       // pair index
    int i = p * 2;
    if (i >= N_EDGES) return;
    int u0, u1, v0, v1;
    if (g_is32) {
        const int2* e = (const int2*)eiv;
        int2 up = e[p];
        int2 vp = ((const int2*)((const int*)eiv + N_EDGES))[p];
        u0 = up.x; u1 = up.y; v0 = vp.x; v1 = vp.y;
    } else {
        const longlong2* e = (const longlong2*)eiv;
        longlong2 up = e[p];
        longlong2 vp = ((const longlong2*)((const long long*)eiv + N_EDGES))[p];
        u0 = (int)up.x; u1 = (int)up.y; v0 = (int)vp.x; v1 = (int)vp.y;
    }
    u0 = min(max(u0, 0), N_NODES - 1); u1 = min(max(u1, 0), N_NODES - 1);
    v0 = min(max(v0, 0), N_NODES - 1); v1 = min(max(v1, 0), N_NODES - 1);
    ((int4*)g_uv)[p] = make_int4(u0, v0, u1, v1);
    atomicAdd(&g_deg[u0], 1);
    atomicAdd(&g_deg[u1], 1);
    atomicAdd(&g_cnt[v0], 1);
    atomicAdd(&g_cnt[v1], 1);
}

// Per-block sums of g_cnt (49 blocks x 1024)
__global__ void __launch_bounds__(1024) k_bsum() {
    int t = threadIdx.x;
    int i = blockIdx.x * 1024 + t;
    int val = (i < N_NODES) ? g_cnt[i] : 0;
#pragma unroll
    for (int o = 16; o; o >>= 1) val += __shfl_xor_sync(0xffffffffu, val, o);
    __shared__ int ws[32];
    if ((t & 31) == 0) ws[t >> 5] = val;
    __syncthreads();
    if (t < 32) {
        int v = ws[t];
#pragma unroll
        for (int o = 16; o; o >>= 1) v += __shfl_xor_sync(0xffffffffu, v, o);
        if (t == 0) g_bsum[blockIdx.x] = v;
    }
}

// Block-local exclusive scan + global base -> g_rowstart
__global__ void __launch_bounds__(1024) k_scan2() {
    int t = threadIdx.x;
    int b = blockIdx.x;
    int i = b * 1024 + t;
    __shared__ int sbase;
    __shared__ int ws[32];
    if (t == 0) {
        int acc = 0;
        for (int j = 0; j < b; j++) acc += g_bsum[j];
        sbase = acc;
    }
    int orig = (i < N_NODES) ? g_cnt[i] : 0;
    int val = orig;
    int lane = t & 31;
#pragma unroll
    for (int o = 1; o < 32; o <<= 1) {
        int n = __shfl_up_sync(0xffffffffu, val, o);
        if (lane >= o) val += n;
    }
    if (lane == 31) ws[t >> 5] = val;
    __syncthreads();
    if (t < 32) {
        int v = ws[t];
#pragma unroll
        for (int o = 1; o < 32; o <<= 1) {
            int n = __shfl_up_sync(0xffffffffu, v, o);
            if (t >= o) v += n;
        }
        ws[t] = v;   // inclusive warp-sums
    }
    __syncthreads();
    int woff = (t >= 32) ? ws[(t >> 5) - 1] : 0;
    int excl = sbase + woff + (val - orig);
    if (i < N_NODES) {
        g_rowstart[i] = excl;
        if (i == N_NODES - 1) g_rowstart[N_NODES] = excl + orig;
    }
}

// Scatter edges into CSR slots (sorted by v); payload = u only
__global__ void __launch_bounds__(256) k_fill() {
    int i = blockIdx.x * 256 + threadIdx.x;
    if (i >= N_EDGES) return;
    int2 uv = g_uv[i];
    int pos = g_rowstart[uv.y] + atomicAdd(&g_fill[uv.y], 1);
    g_csr[pos] = uv.x;
}

// Per-node s factor: svp_v = 1 + dis_v * sum_{u in N(v)} dis_u
__global__ void __launch_bounds__(256) k_svec() {
    int v = blockIdx.x * 256 + threadIdx.x;
    if (v >= N_NODES) return;
    int s = g_rowstart[v], e = g_rowstart[v + 1];
    float s0 = 0.f, s1 = 0.f, s2 = 0.f, s3 = 0.f;
    int i = s;
    for (; i + 4 <= e; i += 4) {
        int u0 = g_csr[i], u1 = g_csr[i+1], u2 = g_csr[i+2], u3 = g_csr[i+3];
        s0 += rsqrtf((float)g_deg[u0] + 1.f);
        s1 += rsqrtf((float)g_deg[u1] + 1.f);
        s2 += rsqrtf((float)g_deg[u2] + 1.f);
        s3 += rsqrtf((float)g_deg[u3] + 1.f);
    }
    for (; i < e; i++) s0 += rsqrtf((float)g_deg[g_csr[i]] + 1.f);
    float sum = (s0 + s1) + (s2 + s3);
    g_svp[v] = 1.f + rsqrtf((float)g_deg[v] + 1.f) * sum;
}

// Composite weights: Wc_l = We_l @ Wu_l, c2_l = be_l @ Wu_l. One block per layer.
__global__ void __launch_bounds__(256) k_wprep(
    const float* __restrict__ We0, const float* __restrict__ Be0, const float* __restrict__ Wu0,
    const float* __restrict__ We1, const float* __restrict__ Be1, const float* __restrict__ Wu1,
    const float* __restrict__ We2, const float* __restrict__ Be2, const float* __restrict__ Wu2)
{
    int l = blockIdx.x;
    const float* We = (l == 0) ? We0 : (l == 1) ? We1 : We2;
    const float* Be = (l == 0) ? Be0 : (l == 1) ? Be1 : Be2;
    const float* Wu = (l == 0) ? Wu0 : (l == 1) ? Wu1 : Wu2;
    __shared__ float sWe[DIM * DIM], sWu[DIM * DIM];
    int t = threadIdx.x;
    for (int i = t; i < DIM * DIM; i += 256) { sWe[i] = We[i]; sWu[i] = Wu[i]; }
    __syncthreads();
    for (int o = t; o < DIM * DIM; o += 256) {
        int i = o >> 6, j = o & 63;
        float acc = 0.f;
#pragma unroll 8
        for (int k = 0; k < DIM; k++)
            acc = fmaf(sWe[i * DIM + k], sWu[k * DIM + j], acc);
        g_Wc[l * DIM * DIM + o] = acc;
    }
    if (t < DIM) {
        float acc = 0.f;
#pragma unroll 8
        for (int k = 0; k < DIM; k++)
            acc = fmaf(Be[k], sWu[k * DIM + t], acc);
        g_c2[l * DIM + t] = acc;
    }
}

// Build layer-0 gather table: g_Hb = bf16(dis[node] * X[node])
__global__ void __launch_bounds__(256) k_hb0(const float* __restrict__ X) {
    int idx = blockIdx.x * 256 + threadIdx.x;   // node*16 + c
    if (idx >= N_NODES * 16) return;
    int node = idx >> 4;
    float dis = rsqrtf((float)g_deg[node] + 1.f);
    float4 v = ((const float4*)X)[idx];
    __nv_bfloat162 b0 = __floats2bfloat162_rn(v.x * dis, v.y * dis);
    __nv_bfloat162 b1 = __floats2bfloat162_rn(v.z * dis, v.w * dis);
    ((uint2*)g_Hb)[idx] = make_uint2(*(unsigned int*)&b0, *(unsigned int*)&b1);
}

// ---------------------------------------------------------------------------
// bf16x2-pair add helper (dis_u pre-folded into Hb)
__device__ __forceinline__ void bf16add(float4& a, uint2 p) {
    float2 lo = __bfloat1622float2(*(__nv_bfloat162*)&p.x);
    float2 hi = __bfloat1622float2(*(__nv_bfloat162*)&p.y);
    a.x += lo.x; a.y += lo.y; a.z += hi.x; a.w += hi.y;
}

// Pull aggregation incl self: P[v] = dis_v * sum_e Hb[u_e] + self[v]
__global__ void __launch_bounds__(256) k_agg(const float* __restrict__ X, int use_gH) {
    int idx = blockIdx.x * 256 + threadIdx.x;
    int node = idx >> 4;
    if (node >= N_NODES) return;
    int c = idx & 15;
    int s = g_rowstart[node];
    int e = g_rowstart[node + 1];
    const uint2* __restrict__ Hb = (const uint2*)g_Hb;
    const float* self = use_gH ? g_Henc : X;

    float4 a0 = make_float4(0.f, 0.f, 0.f, 0.f);
    float4 a1 = make_float4(0.f, 0.f, 0.f, 0.f);
    float4 a2 = make_float4(0.f, 0.f, 0.f, 0.f);
    float4 a3 = make_float4(0.f, 0.f, 0.f, 0.f);

    int i = s;
    for (; i + 4 <= e; i += 4) {
        int u0 = g_csr[i];
        int u1 = g_csr[i + 1];
        int u2 = g_csr[i + 2];
        int u3 = g_csr[i + 3];
        uint2 p0 = Hb[u0 * 16 + c];
        uint2 p1 = Hb[u1 * 16 + c];
        uint2 p2 = Hb[u2 * 16 + c];
        uint2 p3 = Hb[u3 * 16 + c];
        bf16add(a0, p0);
        bf16add(a1, p1);
        bf16add(a2, p2);
        bf16add(a3, p3);
    }
    for (; i < e; i++) {
        uint2 p0 = Hb[g_csr[i] * 16 + c];
        bf16add(a0, p0);
    }

    float dv = rsqrtf((float)g_deg[node] + 1.0f);
    float4 sf = ((const float4*)self)[node * 16 + c];
    float4 acc;
    acc.x = fmaf(dv, (a0.x + a1.x) + (a2.x + a3.x), sf.x);
    acc.y = fmaf(dv, (a0.y + a1.y) + (a2.y + a3.y), sf.y);
    acc.z = fmaf(dv, (a0.z + a1.z) + (a2.z + a3.z), sf.z);
    acc.w = fmaf(dv, (a0.w + a1.w) + (a2.w + a3.w), sf.w);
    ((float4*)g_agg)[node * 16 + c] = acc;
}

// ---------------------------------------------------------------------------
// Half-split layer GEMM: 2 threads per row, each computes 32 output cols.
// 256 threads: row = blk*128 + (tid&127), half = tid>>7 (warp-uniform).
// H' = relu(P @ Wc + bu + svp*c2); writes fp32 to g_Henc, bf16(dis*H') to g_Hb.
__global__ void __launch_bounds__(256) k_layer(
    int l, const float* __restrict__ Bu)
{
    __shared__ float4 Ws[1024];
    __shared__ float  B1[64], B2[64];
    int tid = threadIdx.x;
    const float4* W4 = (const float4*)(g_Wc + l * DIM * DIM);
#pragma unroll
    for (int i = 0; i < 4; i++) Ws[tid + 256 * i] = W4[tid + 256 * i];
    if (tid < 64) { B1[tid] = Bu[tid]; B2[tid] = g_c2[l * DIM + tid]; }
    __syncthreads();

    int row = blockIdx.x * 128 + (tid & 127);
    int h   = tid >> 7;                      // 0 or 1 (warp-uniform)
    if (row >= N_NODES) return;
    float svp = g_svp[row];

    float4 acc[8];
#pragma unroll
    for (int j = 0; j < 8; j++) {
        int c = h * 32 + 4 * j;
        acc[j] = make_float4(fmaf(svp, B2[c],   B1[c]),
                             fmaf(svp, B2[c+1], B1[c+1]),
                             fmaf(svp, B2[c+2], B1[c+2]),
                             fmaf(svp, B2[c+3], B1[c+3]));
    }
    const float4* xr = (const float4*)(g_agg + row * DIM);
#pragma unroll 1
    for (int kk = 0; kk < 16; kk++) {
        float4 hv = xr[kk];
#pragma unroll
        for (int kc = 0; kc < 4; kc++) {
            float hk = (kc == 0) ? hv.x : (kc == 1) ? hv.y : (kc == 2) ? hv.z : hv.w;
            const float4* wrow = Ws + (kk * 4 + kc) * 16 + h * 8;
#pragma unroll
            for (int j = 0; j < 8; j++) {
                float4 w = wrow[j];
                acc[j].x = fmaf(hk, w.x, acc[j].x);
                acc[j].y = fmaf(hk, w.y, acc[j].y);
                acc[j].z = fmaf(hk, w.z, acc[j].z);
                acc[j].w = fmaf(hk, w.w, acc[j].w);
            }
        }
    }

    float dis = rsqrtf((float)g_deg[row] + 1.0f);
    float4* o32 = (float4*)(g_Henc + row * DIM) + h * 8;
    uint2*  ob  = (uint2*)(g_Hb + row * (DIM/2)) + h * 8;
#pragma unroll
    for (int j = 0; j < 8; j++) {
        float4 v = acc[j];
        v.x = fmaxf(v.x, 0.f); v.y = fmaxf(v.y, 0.f);
        v.z = fmaxf(v.z, 0.f); v.w = fmaxf(v.w, 0.f);
        o32[j] = v;
        __nv_bfloat162 b0 = __floats2bfloat162_rn(v.x * dis, v.y * dis);
        __nv_bfloat162 b1 = __floats2bfloat162_rn(v.z * dis, v.w * dis);
        ob[j] = make_uint2(*(unsigned int*)&b0, *(unsigned int*)&b1);
    }
}

// Final half-split layer GEMM + mean-readout + last-block finalize.
__global__ void __launch_bounds__(256) k_layer_sum(
    int l, const float* __restrict__ Bu,
    const float* __restrict__ out_w, const float* __restrict__ out_b,
    float* __restrict__ out)
{
    __shared__ float4 Ws[1024];
    __shared__ float  B1[64], B2[64];
    __shared__ float  ssum[64];
    int tid = threadIdx.x;
    const float4* W4 = (const float4*)(g_Wc + l * DIM * DIM);
#pragma unroll
    for (int i = 0; i < 4; i++) Ws[tid + 256 * i] = W4[tid + 256 * i];
    if (tid < 64) { B1[tid] = Bu[tid]; B2[tid] = g_c2[l * DIM + tid]; ssum[tid] = 0.f; }
    __syncthreads();

    int row = blockIdx.x * 128 + (tid & 127);
    int h   = tid >> 7;
    bool valid = (row < N_NODES);

    float4 acc[8];
    if (valid) {
        float svp = g_svp[row];
#pragma unroll
        for (int j = 0; j < 8; j++) {
            int c = h * 32 + 4 * j;
            acc[j] = make_float4(fmaf(svp, B2[c],   B1[c]),
                                 fmaf(svp, B2[c+1], B1[c+1]),
                                 fmaf(svp, B2[c+2], B1[c+2]),
                                 fmaf(svp, B2[c+3], B1[c+3]));
        }
        const float4* xr = (const float4*)(g_agg + row * DIM);
#pragma unroll 1
        for (int kk = 0; kk < 16; kk++) {
            float4 hv = xr[kk];
#pragma unroll
            for (int kc = 0; kc < 4; kc++) {
                float hk = (kc == 0) ? hv.x : (kc == 1) ? hv.y : (kc == 2) ? hv.z : hv.w;
                const float4* wrow = Ws + (kk * 4 + kc) * 16 + h * 8;
#pragma unroll
                for (int j = 0; j < 8; j++) {
                    float4 w = wrow[j];
                    acc[j].x = fmaf(hk, w.x, acc[j].x);
                    acc[j].y = fmaf(hk, w.y, acc[j].y);
                    acc[j].z = fmaf(hk, w.z, acc[j].z);
                    acc[j].w = fmaf(hk, w.w, acc[j].w);
                }
            }
        }
#pragma unroll
        for (int j = 0; j < 8; j++) {
            acc[j].x = fmaxf(acc[j].x, 0.f); acc[j].y = fmaxf(acc[j].y, 0.f);
            acc[j].z = fmaxf(acc[j].z, 0.f); acc[j].w = fmaxf(acc[j].w, 0.f);
        }
    } else {
#pragma unroll
        for (int j = 0; j < 8; j++) acc[j] = make_float4(0.f, 0.f, 0.f, 0.f);
    }

    // warp is h-uniform: butterfly-reduce 32 cols across 32 rows of the warp
    int lane = tid & 31;
#pragma unroll
    for (int j = 0; j < 8; j++) {
#pragma unroll
        for (int kc = 0; kc < 4; kc++) {
            float v = (kc == 0) ? acc[j].x : (kc == 1) ? acc[j].y : (kc == 2) ? acc[j].z : acc[j].w;
#pragma unroll
            for (int o = 16; o; o >>= 1) v += __shfl_xor_sync(0xffffffffu, v, o);
            if (lane == 0) atomicAdd(&ssum[h * 32 + 4 * j + kc], v);
        }
    }
    __syncthreads();
    if (tid < 64) atomicAdd(&g_sum64[tid], ssum[tid]);

    __threadfence();
    __shared__ int isLast;
    if (tid == 0) {
        int p = atomicAdd(&g_done, 1);
        isLast = (p == (int)gridDim.x - 1) ? 1 : 0;
    }
    __syncthreads();
    if (isLast && tid < 32) {
        float p = g_sum64[tid] * out_w[tid] + g_sum64[tid + 32] * out_w[tid + 32];
#pragma unroll
        for (int o = 16; o; o >>= 1) p += __shfl_down_sync(0xffffffffu, p, o);
        if (tid == 0) out[0] = p / (float)N_NODES + out_b[0];
    }
}

// ---------------------------------------------------------------------------
extern "C" void kernel_launch(void* const* d_in, const int* in_sizes, int n_in,
                              void* d_out, int out_size)
{
    const float* H  = (const float*)d_in[0];
    const void*  ei = d_in[1];
    // d_in[2] = E (unused by reference GCN path)
    const float* enc_w[3] = {(const float*)d_in[3],  (const float*)d_in[7],  (const float*)d_in[11]};
    const float* enc_b[3] = {(const float*)d_in[4],  (const float*)d_in[8],  (const float*)d_in[12]};
    const float* upd_w[3] = {(const float*)d_in[5],  (const float*)d_in[9],  (const float*)d_in[13]};
    const float* upd_b[3] = {(const float*)d_in[6],  (const float*)d_in[10], (const float*)d_in[14]};
    const float* out_w = (const float*)d_in[15];
    const float* out_b = (const float*)d_in[16];
    float* out = (float*)d_out;

    const int EB  = (N_EDGES + 255) / 256;            // 4688
    const int PB  = (N_EDGES / 2 + 255) / 256;        // 2344
    const int NB  = (N_NODES + 255) / 256;            // 196
    const int GB  = (N_NODES + 127) / 128;            // 391 (half-split: 256 thr)
    const int AB  = (N_NODES * 16 + 255) / 256;       // 3125

    k_init <<<NB, 256>>>((const unsigned long long*)ei);
    k_prep <<<PB, 256>>>(ei);
    k_bsum <<<SCAN_B, 1024>>>();
    k_scan2<<<SCAN_B, 1024>>>();
    k_fill <<<EB, 256>>>();
    k_svec <<<NB, 256>>>();
    k_wprep<<<3, 256>>>(enc_w[0], enc_b[0], upd_w[0],
                        enc_w[1], enc_b[1], upd_w[1],
                        enc_w[2], enc_b[2], upd_w[2]);
    k_hb0  <<<AB, 256>>>(H);

    k_agg  <<<AB, 256>>>(H, 0);              // P0 = (S+I)X
    k_layer<<<GB, 256>>>(0, upd_b[0]);       // H1
    k_agg  <<<AB, 256>>>(H, 1);              // P1 = (S+I)H1
    k_layer<<<GB, 256>>>(1, upd_b[1]);       // H2
    k_agg  <<<AB, 256>>>(H, 1);              // P2 = (S+I)H2
    k_layer_sum<<<GB, 256>>>(2, upd_b[2], out_w, out_b, out);
}

// round 13
// speedup vs baseline: 1.0264x; 1.0248x over previous
#include <cuda_runtime.h>
#include <cuda_bf16.h>

#define N_NODES 50000
#define N_EDGES 1200000
#define DIM 64
#define SCAN_B 49   // ceil(50000/1024)

// Scratch (allocation-free __device__ globals)
__device__ __align__(16) float g_Henc[N_NODES * DIM];        // layer output H_l (fp32)
__device__ __align__(16) unsigned int g_Hb[N_NODES * DIM/2]; // bf16x2 of dis[u]*H_l[u]
__device__ __align__(16) float g_agg [N_NODES * DIM];        // P = (S+I)H
__device__ __align__(16) int   g_deg [N_NODES];              // out-degree over u
__device__ __align__(16) int   g_cnt [N_NODES];              // in-degree over v
__device__ __align__(16) int   g_fill[N_NODES];              // fill cursor per v
__device__ __align__(16) int   g_rowstart[N_NODES + 1];      // CSR row offsets (by v)
__device__ __align__(16) int2  g_uv  [N_EDGES];              // decoded (u,v)
__device__ __align__(16) int   g_csr [N_EDGES];              // u sorted by v
__device__ __align__(16) float g_svp [N_NODES];              // 1 + dis_v * sum dis_u
__device__ __align__(16) float g_Wc  [3 * DIM * DIM];        // composite We@Wu per layer
__device__ __align__(16) float g_c2  [3 * DIM];              // be@Wu per layer
__device__ __align__(16) float g_sum64[DIM];
__device__ __align__(16) int   g_bsum[SCAN_B];               // per-block cnt sums
__device__ int g_is32;   // 1 if edge_index is int32 on device
__device__ int g_done;   // last-block ticket for fused readout

// ---------------------------------------------------------------------------
// Init: block 0 probes edge_index dtype; all blocks zero counters/sums.
__global__ void __launch_bounds__(256) k_init(const unsigned long long* __restrict__ ei) {
    int i = blockIdx.x * 256 + threadIdx.x;
    if (i < N_NODES) { g_deg[i] = 0; g_cnt[i] = 0; g_fill[i] = 0; }
    if (i < DIM)     g_sum64[i] = 0.f;
    if (i == 0)      g_done = 0;
    if (blockIdx.x == 0) {
        int t = threadIdx.x;
        unsigned int any = 0;
        for (int j = t; j < 2048; j += 256)
            any |= (unsigned int)(ei[j] >> 32);
        __shared__ unsigned int s;
        if (t == 0) s = 0u;
        __syncthreads();
        atomicOr(&s, any);
        __syncthreads();
        if (t == 0) g_is32 = (s != 0u) ? 1 : 0;
    }
}

// Decode edge index -> int2 uv, histogram deg(u) / cnt(v). 2 edges per thread.
__global__ void __launch_bounds__(256) k_prep(const void* __restrict__ eiv) {
    int p = blockIdx.x * 256 + threadIdx.x;       // pair index
    int i = p * 2;
    if (i >= N_EDGES) return;
    int u0, u1, v0, v1;
    if (g_is32) {
        const int2* e = (const int2*)eiv;
        int2 up = e[p];
        int2 vp = ((const int2*)((const int*)eiv + N_EDGES))[p];
        u0 = up.x; u1 = up.y; v0 = vp.x; v1 = vp.y;
    } else {
        const longlong2* e = (const longlong2*)eiv;
        longlong2 up = e[p];
        longlong2 vp = ((const longlong2*)((const long long*)eiv + N_EDGES))[p];
        u0 = (int)up.x; u1 = (int)up.y; v0 = (int)vp.x; v1 = (int)vp.y;
    }
    u0 = min(max(u0, 0), N_NODES - 1); u1 = min(max(u1, 0), N_NODES - 1);
    v0 = min(max(v0, 0), N_NODES - 1); v1 = min(max(v1, 0), N_NODES - 1);
    ((int4*)g_uv)[p] = make_int4(u0, v0, u1, v1);
    atomicAdd(&g_deg[u0], 1);
    atomicAdd(&g_deg[u1], 1);
    atomicAdd(&g_cnt[v0], 1);
    atomicAdd(&g_cnt[v1], 1);
}

// Per-block sums of g_cnt (49 blocks x 1024)
__global__ void __launch_bounds__(1024) k_bsum() {
    int t = threadIdx.x;
    int i = blockIdx.x * 1024 + t;
    int val = (i < N_NODES) ? g_cnt[i] : 0;
#pragma unroll
    for (int o = 16; o; o >>= 1) val += __shfl_xor_sync(0xffffffffu, val, o);
    __shared__ int ws[32];
    if ((t & 31) == 0) ws[t >> 5] = val;
    __syncthreads();
    if (t < 32) {
        int v = ws[t];
#pragma unroll
        for (int o = 16; o; o >>= 1) v += __shfl_xor_sync(0xffffffffu, v, o);
        if (t == 0) g_bsum[blockIdx.x] = v;
    }
}

// Block-local exclusive scan + global base -> g_rowstart
__global__ void __launch_bounds__(1024) k_scan2() {
    int t = threadIdx.x;
    int b = blockIdx.x;
    int i = b * 1024 + t;
    __shared__ int sbase;
    __shared__ int ws[32];
    if (t == 0) {
        int acc = 0;
        for (int j = 0; j < b; j++) acc += g_bsum[j];
        sbase = acc;
    }
    int orig = (i < N_NODES) ? g_cnt[i] : 0;
    int val = orig;
    int lane = t & 31;
#pragma unroll
    for (int o = 1; o < 32; o <<= 1) {
        int n = __shfl_up_sync(0xffffffffu, val, o);
        if (lane >= o) val += n;
    }
    if (lane == 31) ws[t >> 5] = val;
    __syncthreads();
    if (t < 32) {
        int v = ws[t];
#pragma unroll
        for (int o = 1; o < 32; o <<= 1) {
            int n = __shfl_up_sync(0xffffffffu, v, o);
            if (t >= o) v += n;
        }
        ws[t] = v;   // inclusive warp-sums
    }
    __syncthreads();
    int woff = (t >= 32) ? ws[(t >> 5) - 1] : 0;
    int excl = sbase + woff + (val - orig);
    if (i < N_NODES) {
        g_rowstart[i] = excl;
        if (i == N_NODES - 1) g_rowstart[N_NODES] = excl + orig;
    }
}

// Scatter edges into CSR slots (sorted by v); payload = u only
__global__ void __launch_bounds__(256) k_fill() {
    int i = blockIdx.x * 256 + threadIdx.x;
    if (i >= N_EDGES) return;
    int2 uv = g_uv[i];
    int pos = g_rowstart[uv.y] + atomicAdd(&g_fill[uv.y], 1);
    g_csr[pos] = uv.x;
}

// Per-node s factor: svp_v = 1 + dis_v * sum_{u in N(v)} dis_u
__global__ void __launch_bounds__(256) k_svec() {
    int v = blockIdx.x * 256 + threadIdx.x;
    if (v >= N_NODES) return;
    int s = g_rowstart[v], e = g_rowstart[v + 1];
    float s0 = 0.f, s1 = 0.f, s2 = 0.f, s3 = 0.f;
    int i = s;
    for (; i + 4 <= e; i += 4) {
        int u0 = g_csr[i], u1 = g_csr[i+1], u2 = g_csr[i+2], u3 = g_csr[i+3];
        s0 += rsqrtf((float)g_deg[u0] + 1.f);
        s1 += rsqrtf((float)g_deg[u1] + 1.f);
        s2 += rsqrtf((float)g_deg[u2] + 1.f);
        s3 += rsqrtf((float)g_deg[u3] + 1.f);
    }
    for (; i < e; i++) s0 += rsqrtf((float)g_deg[g_csr[i]] + 1.f);
    float sum = (s0 + s1) + (s2 + s3);
    g_svp[v] = 1.f + rsqrtf((float)g_deg[v] + 1.f) * sum;
}

// Composite weights: Wc_l = We_l @ Wu_l, c2_l = be_l @ Wu_l. One block per layer.
__global__ void __launch_bounds__(256) k_wprep(
    const float* __restrict__ We0, const float* __restrict__ Be0, const float* __restrict__ Wu0,
    const float* __restrict__ We1, const float* __restrict__ Be1, const float* __restrict__ Wu1,
    const float* __restrict__ We2, const float* __restrict__ Be2, const float* __restrict__ Wu2)
{
    int l = blockIdx.x;
    const float* We = (l == 0) ? We0 : (l == 1) ? We1 : We2;
    const float* Be = (l == 0) ? Be0 : (l == 1) ? Be1 : Be2;
    const float* Wu = (l == 0) ? Wu0 : (l == 1) ? Wu1 : Wu2;
    __shared__ float sWe[DIM * DIM], sWu[DIM * DIM];
    int t = threadIdx.x;
    for (int i = t; i < DIM * DIM; i += 256) { sWe[i] = We[i]; sWu[i] = Wu[i]; }
    __syncthreads();
    for (int o = t; o < DIM * DIM; o += 256) {
        int i = o >> 6, j = o & 63;
        float acc = 0.f;
#pragma unroll 8
        for (int k = 0; k < DIM; k++)
            acc = fmaf(sWe[i * DIM + k], sWu[k * DIM + j], acc);
        g_Wc[l * DIM * DIM + o] = acc;
    }
    if (t < DIM) {
        float acc = 0.f;
#pragma unroll 8
        for (int k = 0; k < DIM; k++)
            acc = fmaf(Be[k], sWu[k * DIM + t], acc);
        g_c2[l * DIM + t] = acc;
    }
}

// Build layer-0 gather table: g_Hb = bf16(dis[node] * X[node])
__global__ void __launch_bounds__(256) k_hb0(const float* __restrict__ X) {
    int idx = blockIdx.x * 256 + threadIdx.x;   // node*16 + c
    if (idx >= N_NODES * 16) return;
    int node = idx >> 4;
    float dis = rsqrtf((float)g_deg[node] + 1.f);
    float4 v = ((const float4*)X)[idx];
    __nv_bfloat162 b0 = __floats2bfloat162_rn(v.x * dis, v.y * dis);
    __nv_bfloat162 b1 = __floats2bfloat162_rn(v.z * dis, v.w * dis);
    ((uint2*)g_Hb)[idx] = make_uint2(*(unsigned int*)&b0, *(unsigned int*)&b1);
}

// ---------------------------------------------------------------------------
// bf16x2-pair add helper (dis_u pre-folded into Hb)
__device__ __forceinline__ void bf16add(float4& a, uint2 p) {
    float2 lo = __bfloat1622float2(*(__nv_bfloat162*)&p.x);
    float2 hi = __bfloat1622float2(*(__nv_bfloat162*)&p.y);
    a.x += lo.x; a.y += lo.y; a.z += hi.x; a.w += hi.y;
}

// Pull aggregation incl self: P[v] = dis_v * sum_e Hb[u_e] + self[v]
__global__ void __launch_bounds__(256) k_agg(const float* __restrict__ X, int use_gH) {
    int idx = blockIdx.x * 256 + threadIdx.x;
    int node = idx >> 4;
    if (node >= N_NODES) return;
    int c = idx & 15;
    int s = g_rowstart[node];
    int e = g_rowstart[node + 1];
    const uint2* __restrict__ Hb = (const uint2*)g_Hb;
    const float* self = use_gH ? g_Henc : X;

    float4 a0 = make_float4(0.f, 0.f, 0.f, 0.f);
    float4 a1 = make_float4(0.f, 0.f, 0.f, 0.f);
    float4 a2 = make_float4(0.f, 0.f, 0.f, 0.f);
    float4 a3 = make_float4(0.f, 0.f, 0.f, 0.f);

    int i = s;
    for (; i + 4 <= e; i += 4) {
        int u0 = g_csr[i];
        int u1 = g_csr[i + 1];
        int u2 = g_csr[i + 2];
        int u3 = g_csr[i + 3];
        uint2 p0 = Hb[u0 * 16 + c];
        uint2 p1 = Hb[u1 * 16 + c];
        uint2 p2 = Hb[u2 * 16 + c];
        uint2 p3 = Hb[u3 * 16 + c];
        bf16add(a0, p0);
        bf16add(a1, p1);
        bf16add(a2, p2);
        bf16add(a3, p3);
    }
    for (; i < e; i++) {
        uint2 p0 = Hb[g_csr[i] * 16 + c];
        bf16add(a0, p0);
    }

    float dv = rsqrtf((float)g_deg[node] + 1.0f);
    float4 sf = ((const float4*)self)[node * 16 + c];
    float4 acc;
    acc.x = fmaf(dv, (a0.x + a1.x) + (a2.x + a3.x), sf.x);
    acc.y = fmaf(dv, (a0.y + a1.y) + (a2.y + a3.y), sf.y);
    acc.z = fmaf(dv, (a0.z + a1.z) + (a2.z + a3.z), sf.z);
    acc.w = fmaf(dv, (a0.w + a1.w) + (a2.w + a3.w), sf.w);
    ((float4*)g_agg)[node * 16 + c] = acc;
}

// ---------------------------------------------------------------------------
// Packed f32x2 helpers
__device__ __forceinline__ void ffma2(unsigned long long& d,
                                      unsigned long long a,
                                      unsigned long long b) {
    asm("fma.rn.f32x2 %0, %1, %2, %0;" : "+l"(d) : "l"(a), "l"(b));
}
__device__ __forceinline__ unsigned long long pack2(float lo, float hi) {
    unsigned long long r;
    asm("mov.b64 %0, {%1, %2};" : "=l"(r) : "f"(lo), "f"(hi));
    return r;
}
__device__ __forceinline__ void unpack2(unsigned long long v, float& lo, float& hi) {
    asm("mov.b64 {%0, %1}, %2;" : "=f"(lo), "=f"(hi) : "l"(v));
}

// Layer GEMM core with FFMA2: row x (in-loop loads) @ Ws2 -> 32 packed acc.
// Ws2: [64 k][32 pairs] as ull; warp-uniform LDS.128 (2 pairs per load).
__device__ __forceinline__ void gemm_f32x2(
    const float4* __restrict__ xr,
    const unsigned long long* __restrict__ Ws2,
    unsigned long long* __restrict__ acc)
{
#pragma unroll 1
    for (int kk = 0; kk < 16; kk++) {
        float4 hv = xr[kk];
#pragma unroll
        for (int kc = 0; kc < 4; kc++) {
            float hk = (kc == 0) ? hv.x : (kc == 1) ? hv.y : (kc == 2) ? hv.z : hv.w;
            unsigned long long hk2 = pack2(hk, hk);
            const ulonglong2* wrow = (const ulonglong2*)(Ws2 + (kk * 4 + kc) * 32);
#pragma unroll
            for (int j = 0; j < 16; j++) {
                ulonglong2 w = wrow[j];
                ffma2(acc[2 * j],     hk2, w.x);
                ffma2(acc[2 * j + 1], hk2, w.y);
            }
        }
    }
}

// Layer GEMM (one per layer): H' = relu(P @ Wc + bu + svp*c2).
// One row per thread, FFMA2 accumulators.
__global__ void __launch_bounds__(128) k_layer(
    int l, const float* __restrict__ Bu)
{
    __shared__ unsigned long long Ws2[2048];   // 64 k x 32 pairs
    __shared__ float B1[64], B2[64];
    int tid = threadIdx.x;
    const ulonglong2* W8 = (const ulonglong2*)(g_Wc + l * DIM * DIM);
    ulonglong2* S8 = (ulonglong2*)Ws2;
#pragma unroll
    for (int i = 0; i < 8; i++) S8[tid + 128 * i] = W8[tid + 128 * i];
    if (tid < 64) { B1[tid] = Bu[tid]; B2[tid] = g_c2[l * DIM + tid]; }
    __syncthreads();

    int row = blockIdx.x * 128 + tid;
    if (row >= N_NODES) return;
    float svp = g_svp[row];

    unsigned long long acc[32];
#pragma unroll
    for (int j = 0; j < 32; j++)
        acc[j] = pack2(fmaf(svp, B2[2*j],   B1[2*j]),
                       fmaf(svp, B2[2*j+1], B1[2*j+1]));

    gemm_f32x2((const float4*)(g_agg + row * DIM), Ws2, acc);

    float dis = rsqrtf((float)g_deg[row] + 1.0f);
    float4* o32 = (float4*)(g_Henc + row * DIM);
    uint2*  ob  = (uint2*)(g_Hb + row * (DIM/2));
#pragma unroll
    for (int j = 0; j < 16; j++) {
        float a, b, c, d;
        unpack2(acc[2*j],     a, b);
        unpack2(acc[2*j + 1], c, d);
        a = fmaxf(a, 0.f); b = fmaxf(b, 0.f);
        c = fmaxf(c, 0.f); d = fmaxf(d, 0.f);
        o32[j] = make_float4(a, b, c, d);
        __nv_bfloat162 b0 = __floats2bfloat162_rn(a * dis, b * dis);
        __nv_bfloat162 b1 = __floats2bfloat162_rn(c * dis, d * dis);
        ob[j] = make_uint2(*(unsigned int*)&b0, *(unsigned int*)&b1);
    }
}

// Final layer GEMM + mean-readout + last-block finalize (FFMA2).
__global__ void __launch_bounds__(128) k_layer_sum(
    int l, const float* __restrict__ Bu,
    const float* __restrict__ out_w, const float* __restrict__ out_b,
    float* __restrict__ out)
{
    __shared__ unsigned long long Ws2[2048];
    __shared__ float B1[64], B2[64];
    __shared__ float ssum[64];
    int tid = threadIdx.x;
    const ulonglong2* W8 = (const ulonglong2*)(g_Wc + l * DIM * DIM);
    ulonglong2* S8 = (ulonglong2*)Ws2;
#pragma unroll
    for (int i = 0; i < 8; i++) S8[tid + 128 * i] = W8[tid + 128 * i];
    if (tid < 64) { B1[tid] = Bu[tid]; B2[tid] = g_c2[l * DIM + tid]; ssum[tid] = 0.f; }
    __syncthreads();

    int row = blockIdx.x * 128 + tid;
    bool valid = (row < N_NODES);

    float h[64];
    if (valid) {
        float svp = g_svp[row];
        unsigned long long acc[32];
#pragma unroll
        for (int j = 0; j < 32; j++)
            acc[j] = pack2(fmaf(svp, B2[2*j],   B1[2*j]),
                           fmaf(svp, B2[2*j+1], B1[2*j+1]));
        gemm_f32x2((const float4*)(g_agg + row * DIM), Ws2, acc);
#pragma unroll
        for (int j = 0; j < 32; j++) {
            float lo, hi;
            unpack2(acc[j], lo, hi);
            h[2*j]   = fmaxf(lo, 0.f);
            h[2*j+1] = fmaxf(hi, 0.f);
        }
    } else {
#pragma unroll
        for (int j = 0; j < 64; j++) h[j] = 0.f;
    }

    int lane = tid & 31;
#pragma unroll
    for (int j = 0; j < 64; j++) {
        float v = h[j];
#pragma unroll
        for (int o = 16; o; o >>= 1) v += __shfl_xor_sync(0xffffffffu, v, o);
        if (lane == 0) atomicAdd(&ssum[j], v);
    }
    __syncthreads();
    if (tid < 64) atomicAdd(&g_sum64[tid], ssum[tid]);

    __threadfence();
    __shared__ int isLast;
    if (tid == 0) {
        int p = atomicAdd(&g_done, 1);
        isLast = (p == (int)gridDim.x - 1) ? 1 : 0;
    }
    __syncthreads();
    if (isLast && tid < 32) {
        float p = g_sum64[tid] * out_w[tid] + g_sum64[tid + 32] * out_w[tid + 32];
#pragma unroll
        for (int o = 16; o; o >>= 1) p += __shfl_down_sync(0xffffffffu, p, o);
        if (tid == 0) out[0] = p / (float)N_NODES + out_b[0];
    }
}

// ---------------------------------------------------------------------------
extern "C" void kernel_launch(void* const* d_in, const int* in_sizes, int n_in,
                              void* d_out, int out_size)
{
    const float* H  = (const float*)d_in[0];
    const void*  ei = d_in[1];
    // d_in[2] = E (unused by reference GCN path)
    const float* enc_w[3] = {(const float*)d_in[3],  (const float*)d_in[7],  (const float*)d_in[11]};
    const float* enc_b[3] = {(const float*)d_in[4],  (const float*)d_in[8],  (const float*)d_in[12]};
    const float* upd_w[3] = {(const float*)d_in[5],  (const float*)d_in[9],  (const float*)d_in[13]};
    const float* upd_b[3] = {(const float*)d_in[6],  (const float*)d_in[10], (const float*)d_in[14]};
    const float* out_w = (const float*)d_in[15];
    const float* out_b = (const float*)d_in[16];
    float* out = (float*)d_out;

    const int EB  = (N_EDGES + 255) / 256;            // 4688
    const int PB  = (N_EDGES / 2 + 255) / 256;        // 2344
    const int NB  = (N_NODES + 255) / 256;            // 196
    const int GB  = (N_NODES + 127) / 128;            // 391
    const int AB  = (N_NODES * 16 + 255) / 256;       // 3125

    k_init <<<NB, 256>>>((const unsigned long long*)ei);
    k_prep <<<PB, 256>>>(ei);
    k_bsum <<<SCAN_B, 1024>>>();
    k_scan2<<<SCAN_B, 1024>>>();
    k_fill <<<EB, 256>>>();
    k_svec <<<NB, 256>>>();
    k_wprep<<<3, 256>>>(enc_w[0], enc_b[0], upd_w[0],
                        enc_w[1], enc_b[1], upd_w[1],
                        enc_w[2], enc_b[2], upd_w[2]);
    k_hb0  <<<AB, 256>>>(H);

    k_agg  <<<AB, 256>>>(H, 0);              // P0 = (S+I)X
    k_layer<<<GB, 128>>>(0, upd_b[0]);       // H1
    k_agg  <<<AB, 256>>>(H, 1);              // P1 = (S+I)H1
    k_layer<<<GB, 128>>>(1, upd_b[1]);       // H2
    k_agg  <<<AB, 256>>>(H, 1);              // P2 = (S+I)H2
    k_layer_sum<<<GB, 128>>>(2, upd_b[2], out_w, out_b, out);
}

// round 14
// speedup vs baseline: 1.0391x; 1.0124x over previous
#include <cuda_runtime.h>
#include <cuda_bf16.h>

#define N_NODES 50000
#define N_EDGES 1200000
#define DIM 64
#define SCAN_B 49   // ceil(50000/1024)

// Scratch (allocation-free __device__ globals)
__device__ __align__(16) float g_Henc[N_NODES * DIM];        // layer output H_l (fp32)
__device__ __align__(16) unsigned int g_Hb[N_NODES * DIM/2]; // bf16x2 of dis[u]*H_l[u]
__device__ __align__(16) float g_agg [N_NODES * DIM];        // P = (S+I)H
__device__ __align__(16) int   g_deg [N_NODES];              // out-degree over u
__device__ __align__(16) int   g_cnt [N_NODES];              // in-degree over v
__device__ __align__(16) int   g_rowstart[N_NODES + 1];      // CSR row offsets (by v)
__device__ __align__(16) int2  g_uv  [N_EDGES];              // decoded (u,v)
__device__ __align__(16) int   g_rank[N_EDGES];              // rank of edge within row v
__device__ __align__(16) int   g_csr [N_EDGES];              // u sorted by v
__device__ __align__(16) float g_dis [N_NODES];              // rsqrt(deg+1)
__device__ __align__(16) float g_svs [N_NODES];              // sum_{u in N(v)} dis_u
__device__ __align__(16) float g_svp [N_NODES];              // 1 + dis_v * svs_v
__device__ __align__(16) float g_Wc  [3 * DIM * DIM];        // composite We@Wu per layer
__device__ __align__(16) float g_c2  [3 * DIM];              // be@Wu per layer
__device__ __align__(16) float g_sum64[DIM];
__device__ __align__(16) int   g_bsum[SCAN_B];               // per-block cnt sums
__device__ int g_is32;   // 1 if edge_index is int32 on device
__device__ int g_done;   // last-block ticket for fused readout

// ---------------------------------------------------------------------------
// Init: block 0 probes edge_index dtype; all blocks zero counters/sums.
__global__ void __launch_bounds__(256) k_init(const unsigned long long* __restrict__ ei) {
    int i = blockIdx.x * 256 + threadIdx.x;
    if (i < N_NODES) { g_deg[i] = 0; g_cnt[i] = 0; g_svs[i] = 0.f; }
    if (i < DIM)     g_sum64[i] = 0.f;
    if (i == 0)      g_done = 0;
    if (blockIdx.x == 0) {
        int t = threadIdx.x;
        unsigned int any = 0;
        for (int j = t; j < 2048; j += 256)
            any |= (unsigned int)(ei[j] >> 32);
        __shared__ unsigned int s;
        if (t == 0) s = 0u;
        __syncthreads();
        atomicOr(&s, any);
        __syncthreads();
        if (t == 0) g_is32 = (s != 0u) ? 1 : 0;
    }
}

// Decode edge index -> uv + rank, histogram deg(u) / cnt(v). 2 edges per thread.
// The cnt atomicAdd's return value IS the edge's rank within row v (free).
__global__ void __launch_bounds__(256) k_prep(const void* __restrict__ eiv) {
    int p = blockIdx.x * 256 + threadIdx.x;       // pair index
    int i = p * 2;
    if (i >= N_EDGES) return;
    int u0, u1, v0, v1;
    if (g_is32) {
        const int2* e = (const int2*)eiv;
        int2 up = e[p];
        int2 vp = ((const int2*)((const int*)eiv + N_EDGES))[p];
        u0 = up.x; u1 = up.y; v0 = vp.x; v1 = vp.y;
    } else {
        const longlong2* e = (const longlong2*)eiv;
        longlong2 up = e[p];
        longlong2 vp = ((const longlong2*)((const long long*)eiv + N_EDGES))[p];
        u0 = (int)up.x; u1 = (int)up.y; v0 = (int)vp.x; v1 = (int)vp.y;
    }
    u0 = min(max(u0, 0), N_NODES - 1); u1 = min(max(u1, 0), N_NODES - 1);
    v0 = min(max(v0, 0), N_NODES - 1); v1 = min(max(v1, 0), N_NODES - 1);
    ((int4*)g_uv)[p] = make_int4(u0, v0, u1, v1);
    atomicAdd(&g_deg[u0], 1);
    atomicAdd(&g_deg[u1], 1);
    int r0 = atomicAdd(&g_cnt[v0], 1);
    int r1 = atomicAdd(&g_cnt[v1], 1);
    ((int2*)g_rank)[p] = make_int2(r0, r1);
}

// Per-block sums of g_cnt (49 blocks x 1024); also precompute dis = rsqrt(deg+1)
__global__ void __launch_bounds__(1024) k_bsum() {
    int t = threadIdx.x;
    int i = blockIdx.x * 1024 + t;
    int val = 0;
    if (i < N_NODES) {
        val = g_cnt[i];
        g_dis[i] = rsqrtf((float)g_deg[i] + 1.0f);
    }
#pragma unroll
    for (int o = 16; o; o >>= 1) val += __shfl_xor_sync(0xffffffffu, val, o);
    __shared__ int ws[32];
    if ((t & 31) == 0) ws[t >> 5] = val;
    __syncthreads();
    if (t < 32) {
        int v = ws[t];
#pragma unroll
        for (int o = 16; o; o >>= 1) v += __shfl_xor_sync(0xffffffffu, v, o);
        if (t == 0) g_bsum[blockIdx.x] = v;
    }
}

// Block-local exclusive scan + global base -> g_rowstart
__global__ void __launch_bounds__(1024) k_scan2() {
    int t = threadIdx.x;
    int b = blockIdx.x;
    int i = b * 1024 + t;
    __shared__ int sbase;
    __shared__ int ws[32];
    if (t == 0) {
        int acc = 0;
        for (int j = 0; j < b; j++) acc += g_bsum[j];
        sbase = acc;
    }
    int orig = (i < N_NODES) ? g_cnt[i] : 0;
    int val = orig;
    int lane = t & 31;
#pragma unroll
    for (int o = 1; o < 32; o <<= 1) {
        int n = __shfl_up_sync(0xffffffffu, val, o);
        if (lane >= o) val += n;
    }
    if (lane == 31) ws[t >> 5] = val;
    __syncthreads();
    if (t < 32) {
        int v = ws[t];
#pragma unroll
        for (int o = 1; o < 32; o <<= 1) {
            int n = __shfl_up_sync(0xffffffffu, v, o);
            if (t >= o) v += n;
        }
        ws[t] = v;   // inclusive warp-sums
    }
    __syncthreads();
    int woff = (t >= 32) ? ws[(t >> 5) - 1] : 0;
    int excl = sbase + woff + (val - orig);
    if (i < N_NODES) {
        g_rowstart[i] = excl;
        if (i == N_NODES - 1) g_rowstart[N_NODES] = excl + orig;
    }
}

// Scatter edges into CSR slots via precomputed rank (NO atomics for position);
// also accumulate svs[v] += dis[u] (spread float atomics).
__global__ void __launch_bounds__(256) k_fill() {
    int i = blockIdx.x * 256 + threadIdx.x;
    if (i >= N_EDGES) return;
    int2 uv = g_uv[i];
    int pos = g_rowstart[uv.y] + g_rank[i];
    g_csr[pos] = uv.x;
    atomicAdd(&g_svs[uv.y], g_dis[uv.x]);
}

// Composite weights: Wc_l = We_l @ Wu_l, c2_l = be_l @ Wu_l. One block per layer.
__global__ void __launch_bounds__(256) k_wprep(
    const float* __restrict__ We0, const float* __restrict__ Be0, const float* __restrict__ Wu0,
    const float* __restrict__ We1, const float* __restrict__ Be1, const float* __restrict__ Wu1,
    const float* __restrict__ We2, const float* __restrict__ Be2, const float* __restrict__ Wu2)
{
    int l = blockIdx.x;
    const float* We = (l == 0) ? We0 : (l == 1) ? We1 : We2;
    const float* Be = (l == 0) ? Be0 : (l == 1) ? Be1 : Be2;
    const float* Wu = (l == 0) ? Wu0 : (l == 1) ? Wu1 : Wu2;
    __shared__ float sWe[DIM * DIM], sWu[DIM * DIM];
    int t = threadIdx.x;
    for (int i = t; i < DIM * DIM; i += 256) { sWe[i] = We[i]; sWu[i] = Wu[i]; }
    __syncthreads();
    for (int o = t; o < DIM * DIM; o += 256) {
        int i = o >> 6, j = o & 63;
        float acc = 0.f;
#pragma unroll 8
        for (int k = 0; k < DIM; k++)
            acc = fmaf(sWe[i * DIM + k], sWu[k * DIM + j], acc);
        g_Wc[l * DIM * DIM + o] = acc;
    }
    if (t < DIM) {
        float acc = 0.f;
#pragma unroll 8
        for (int k = 0; k < DIM; k++)
            acc = fmaf(Be[k], sWu[k * DIM + t], acc);
        g_c2[l * DIM + t] = acc;
    }
}

// Build layer-0 gather table g_Hb = bf16(dis*X) and finalize svp (lane 0).
__global__ void __launch_bounds__(256) k_hb0(const float* __restrict__ X) {
    int idx = blockIdx.x * 256 + threadIdx.x;   // node*16 + c
    if (idx >= N_NODES * 16) return;
    int node = idx >> 4;
    float dis = g_dis[node];
    if ((idx & 15) == 0)
        g_svp[node] = 1.f + dis * g_svs[node];
    float4 v = ((const float4*)X)[idx];
    __nv_bfloat162 b0 = __floats2bfloat162_rn(v.x * dis, v.y * dis);
    __nv_bfloat162 b1 = __floats2bfloat162_rn(v.z * dis, v.w * dis);
    ((uint2*)g_Hb)[idx] = make_uint2(*(unsigned int*)&b0, *(unsigned int*)&b1);
}

// ---------------------------------------------------------------------------
// bf16x2-pair add helper (dis_u pre-folded into Hb)
__device__ __forceinline__ void bf16add(float4& a, uint2 p) {
    float2 lo = __bfloat1622float2(*(__nv_bfloat162*)&p.x);
    float2 hi = __bfloat1622float2(*(__nv_bfloat162*)&p.y);
    a.x += lo.x; a.y += lo.y; a.z += hi.x; a.w += hi.y;
}

// Pull aggregation incl self: P[v] = dis_v * sum_e Hb[u_e] + self[v]
__global__ void __launch_bounds__(256) k_agg(const float* __restrict__ X, int use_gH) {
    int idx = blockIdx.x * 256 + threadIdx.x;
    int node = idx >> 4;
    if (node >= N_NODES) return;
    int c = idx & 15;
    int s = g_rowstart[node];
    int e = g_rowstart[node + 1];
    const uint2* __restrict__ Hb = (const uint2*)g_Hb;
    const float* self = use_gH ? g_Henc : X;

    float4 a0 = make_float4(0.f, 0.f, 0.f, 0.f);
    float4 a1 = make_float4(0.f, 0.f, 0.f, 0.f);
    float4 a2 = make_float4(0.f, 0.f, 0.f, 0.f);
    float4 a3 = make_float4(0.f, 0.f, 0.f, 0.f);

    int i = s;
    for (; i + 4 <= e; i += 4) {
        int u0 = g_csr[i];
        int u1 = g_csr[i + 1];
        int u2 = g_csr[i + 2];
        int u3 = g_csr[i + 3];
        uint2 p0 = Hb[u0 * 16 + c];
        uint2 p1 = Hb[u1 * 16 + c];
        uint2 p2 = Hb[u2 * 16 + c];
        uint2 p3 = Hb[u3 * 16 + c];
        bf16add(a0, p0);
        bf16add(a1, p1);
        bf16add(a2, p2);
        bf16add(a3, p3);
    }
    for (; i < e; i++) {
        uint2 p0 = Hb[g_csr[i] * 16 + c];
        bf16add(a0, p0);
    }

    float dv = g_dis[node];
    float4 sf = ((const float4*)self)[node * 16 + c];
    float4 acc;
    acc.x = fmaf(dv, (a0.x + a1.x) + (a2.x + a3.x), sf.x);
    acc.y = fmaf(dv, (a0.y + a1.y) + (a2.y + a3.y), sf.y);
    acc.z = fmaf(dv, (a0.z + a1.z) + (a2.z + a3.z), sf.z);
    acc.w = fmaf(dv, (a0.w + a1.w) + (a2.w + a3.w), sf.w);
    ((float4*)g_agg)[node * 16 + c] = acc;
}

// ---------------------------------------------------------------------------
// Packed f32x2 helpers
__device__ __forceinline__ void ffma2(unsigned long long& d,
                                      unsigned long long a,
                                      unsigned long long b) {
    asm("fma.rn.f32x2 %0, %1, %2, %0;" : "+l"(d) : "l"(a), "l"(b));
}
__device__ __forceinline__ unsigned long long pack2(float lo, float hi) {
    unsigned long long r;
    asm("mov.b64 %0, {%1, %2};" : "=l"(r) : "f"(lo), "f"(hi));
    return r;
}
__device__ __forceinline__ void unpack2(unsigned long long v, float& lo, float& hi) {
    asm("mov.b64 {%0, %1}, %2;" : "=f"(lo), "=f"(hi) : "l"(v));
}

// Layer GEMM core with FFMA2: row x (in-loop loads) @ Ws2 -> 32 packed acc.
__device__ __forceinline__ void gemm_f32x2(
    const float4* __restrict__ xr,
    const unsigned long long* __restrict__ Ws2,
    unsigned long long* __restrict__ acc)
{
#pragma unroll 1
    for (int kk = 0; kk < 16; kk++) {
        float4 hv = xr[kk];
#pragma unroll
        for (int kc = 0; kc < 4; kc++) {
            float hk = (kc == 0) ? hv.x : (kc == 1) ? hv.y : (kc == 2) ? hv.z : hv.w;
            unsigned long long hk2 = pack2(hk, hk);
            const ulonglong2* wrow = (const ulonglong2*)(Ws2 + (kk * 4 + kc) * 32);
#pragma unroll
            for (int j = 0; j < 16; j++) {
                ulonglong2 w = wrow[j];
                ffma2(acc[2 * j],     hk2, w.x);
                ffma2(acc[2 * j + 1], hk2, w.y);
            }
        }
    }
}

// Layer GEMM (one per layer): H' = relu(P @ Wc + bu + svp*c2).
__global__ void __launch_bounds__(128) k_layer(
    int l, const float* __restrict__ Bu)
{
    __shared__ unsigned long long Ws2[2048];   // 64 k x 32 pairs
    __shared__ float B1[64], B2[64];
    int tid = threadIdx.x;
    const ulonglong2* W8 = (const ulonglong2*)(g_Wc + l * DIM * DIM);
    ulonglong2* S8 = (ulonglong2*)Ws2;
#pragma unroll
    for (int i = 0; i < 8; i++) S8[tid + 128 * i] = W8[tid + 128 * i];
    if (tid < 64) { B1[tid] = Bu[tid]; B2[tid] = g_c2[l * DIM + tid]; }
    __syncthreads();

    int row = blockIdx.x * 128 + tid;
    if (row >= N_NODES) return;
    float svp = g_svp[row];

    unsigned long long acc[32];
#pragma unroll
    for (int j = 0; j < 32; j++)
        acc[j] = pack2(fmaf(svp, B2[2*j],   B1[2*j]),
                       fmaf(svp, B2[2*j+1], B1[2*j+1]));

    gemm_f32x2((const float4*)(g_agg + row * DIM), Ws2, acc);

    float dis = g_dis[row];
    float4* o32 = (float4*)(g_Henc + row * DIM);
    uint2*  ob  = (uint2*)(g_Hb + row * (DIM/2));
#pragma unroll
    for (int j = 0; j < 16; j++) {
        float a, b, c, d;
        unpack2(acc[2*j],     a, b);
        unpack2(acc[2*j + 1], c, d);
        a = fmaxf(a, 0.f); b = fmaxf(b, 0.f);
        c = fmaxf(c, 0.f); d = fmaxf(d, 0.f);
        o32[j] = make_float4(a, b, c, d);
        __nv_bfloat162 b0 = __floats2bfloat162_rn(a * dis, b * dis);
        __nv_bfloat162 b1 = __floats2bfloat162_rn(c * dis, d * dis);
        ob[j] = make_uint2(*(unsigned int*)&b0, *(unsigned int*)&b1);
    }
}

// Final layer GEMM + mean-readout + last-block finalize (FFMA2).
__global__ void __launch_bounds__(128) k_layer_sum(
    int l, const float* __restrict__ Bu,
    const float* __restrict__ out_w, const float* __restrict__ out_b,
    float* __restrict__ out)
{
    __shared__ unsigned long long Ws2[2048];
    __shared__ float B1[64], B2[64];
    __shared__ float ssum[64];
    int tid = threadIdx.x;
    const ulonglong2* W8 = (const ulonglong2*)(g_Wc + l * DIM * DIM);
    ulonglong2* S8 = (ulonglong2*)Ws2;
#pragma unroll
    for (int i = 0; i < 8; i++) S8[tid + 128 * i] = W8[tid + 128 * i];
    if (tid < 64) { B1[tid] = Bu[tid]; B2[tid] = g_c2[l * DIM + tid]; ssum[tid] = 0.f; }
    __syncthreads();

    int row = blockIdx.x * 128 + tid;
    bool valid = (row < N_NODES);

    float h[64];
    if (valid) {
        float svp = g_svp[row];
        unsigned long long acc[32];
#pragma unroll
        for (int j = 0; j < 32; j++)
            acc[j] = pack2(fmaf(svp, B2[2*j],   B1[2*j]),
                           fmaf(svp, B2[2*j+1], B1[2*j+1]));
        gemm_f32x2((const float4*)(g_agg + row * DIM), Ws2, acc);
#pragma unroll
        for (int j = 0; j < 32; j++) {
            float lo, hi;
            unpack2(acc[j], lo, hi);
            h[2*j]   = fmaxf(lo, 0.f);
            h[2*j+1] = fmaxf(hi, 0.f);
        }
    } else {
#pragma unroll
        for (int j = 0; j < 64; j++) h[j] = 0.f;
    }

    int lane = tid & 31;
#pragma unroll
    for (int j = 0; j < 64; j++) {
        float v = h[j];
#pragma unroll
        for (int o = 16; o; o >>= 1) v += __shfl_xor_sync(0xffffffffu, v, o);
        if (lane == 0) atomicAdd(&ssum[j], v);
    }
    __syncthreads();
    if (tid < 64) atomicAdd(&g_sum64[tid], ssum[tid]);

    __threadfence();
    __shared__ int isLast;
    if (tid == 0) {
        int p = atomicAdd(&g_done, 1);
        isLast = (p == (int)gridDim.x - 1) ? 1 : 0;
    }
    __syncthreads();
    if (isLast && tid < 32) {
        float p = g_sum64[tid] * out_w[tid] + g_sum64[tid + 32] * out_w[tid + 32];
#pragma unroll
        for (int o = 16; o; o >>= 1) p += __shfl_down_sync(0xffffffffu, p, o);
        if (tid == 0) out[0] = p / (float)N_NODES + out_b[0];
    }
}

// ---------------------------------------------------------------------------
extern "C" void kernel_launch(void* const* d_in, const int* in_sizes, int n_in,
                              void* d_out, int out_size)
{
    const float* H  = (const float*)d_in[0];
    const void*  ei = d_in[1];
    // d_in[2] = E (unused by reference GCN path)
    const float* enc_w[3] = {(const float*)d_in[3],  (const float*)d_in[7],  (const float*)d_in[11]};
    const float* enc_b[3] = {(const float*)d_in[4],  (const float*)d_in[8],  (const float*)d_in[12]};
    const float* upd_w[3] = {(const float*)d_in[5],  (const float*)d_in[9],  (const float*)d_in[13]};
    const float* upd_b[3] = {(const float*)d_in[6],  (const float*)d_in[10], (const float*)d_in[14]};
    const float* out_w = (const float*)d_in[15];
    const float* out_b = (const float*)d_in[16];
    float* out = (float*)d_out;

    const int EB  = (N_EDGES + 255) / 256;            // 4688
    const int PB  = (N_EDGES / 2 + 255) / 256;        // 2344
    const int NB  = (N_NODES + 255) / 256;            // 196
    const int GB  = (N_NODES + 127) / 128;            // 391
    const int AB  = (N_NODES * 16 + 255) / 256;       // 3125

    k_init <<<NB, 256>>>((const unsigned long long*)ei);
    k_prep <<<PB, 256>>>(ei);
    k_bsum <<<SCAN_B, 1024>>>();
    k_scan2<<<SCAN_B, 1024>>>();
    k_fill <<<EB, 256>>>();
    k_wprep<<<3, 256>>>(enc_w[0], enc_b[0], upd_w[0],
                        enc_w[1], enc_b[1], upd_w[1],
                        enc_w[2], enc_b[2], upd_w[2]);
    k_hb0  <<<AB, 256>>>(H);

    k_agg  <<<AB, 256>>>(H, 0);              // P0 = (S+I)X
    k_layer<<<GB, 128>>>(0, upd_b[0]);       // H1
    k_agg  <<<AB, 256>>>(H, 1);              // P1 = (S+I)H1
    k_layer<<<GB, 128>>>(1, upd_b[1]);       // H2
    k_agg  <<<AB, 256>>>(H, 1);              // P2 = (S+I)H2
    k_layer_sum<<<GB, 128>>>(2, upd_b[2], out_w, out_b, out);
}